// round 11
// baseline (speedup 1.0000x reference)
#include <cuda_runtime.h>

// PBKDF2-toy, serial single-warp register kernel. R11: clean re-run of the
// 152/152 pipe-balance experiment (R9's goal without R9's asm damage).
// Base = R8 (best, 184.4us): absorb collapsed, unroll 4, mix adds plain C++
// (ptxas pressure-balances them onto IMAD/fma). Only change: F accumulator
// = 8 packed halfword pairs (pack16 IMAD + LOP3) + 16 single XORs, fused
// into mix round 4 -> forced-alu 152, fma 152, pipe floor 320 -> 304.
// Decisive: ~176us confirms per-pipe rt=2 binding; neutral means the total
// -issue floor (304) already binds and 184 is the formulation optimum.
// Harness dtype shims: float32 out, dtype-sniffed in (proven R3).

__device__ __forceinline__ unsigned load_byte(const void* p, int i) {
    int v = ((const int*)p)[i];
    if ((unsigned)v <= 255u) return (unsigned)v;   // int32 input
    return (unsigned)(int)__int_as_float(v);       // float32 input
}

// hi*65536 + lo as a single IMAD (fma pipe); benign to scheduling (R8).
__device__ __forceinline__ unsigned pack16(unsigned hi, unsigned lo) {
    unsigned t;
    asm("mad.lo.u32 %0, %1, 65536, %2;" : "=r"(t) : "r"(hi), "r"(lo));
    return t;
}

__global__ void __launch_bounds__(32, 1)
Model_62955630625117_kernel(const void* __restrict__ pw_in,
                            const void* __restrict__ salt_in,
                            float* __restrict__ out) {
    // All lanes uniform & convergent; lane 0 writes at the end.
    unsigned c[16];    // (pw[j]*31) & 255, loop-invariant
    unsigned r[32];    // hash state U (mix LOP3 keeps bytes 8-bit)
    unsigned Fp[8];    // packed: lo16 = F[j], hi16 = F[j+8]   (j = 0..7)
    unsigned Fh[16];   // singles: F[16..31]

    #pragma unroll
    for (int j = 0; j < 16; j++) {
        unsigned p = load_byte(pw_in, j);
        c[j] = (p * 31u) & 255u;
        r[j] = p;
    }
    #pragma unroll
    for (int j = 0; j < 16; j++) r[16 + j] = load_byte(salt_in, j);

    // First hmac message = salt(16) ++ block_num{0,0,0,1}
    r[0] = c[0];
    r[1] = c[1];
    r[2] = c[2];
    r[3] = (c[3] + 1u) & 255u;

    // U0 mix
    #pragma unroll
    for (int rd = 0; rd < 4; rd++) {
        #pragma unroll
        for (int i = 0; i < 32; i++)
            r[i] = (r[i] ^ (r[(i + 17) & 31] + r[(i + 11) & 31])) & 255u;
    }
    #pragma unroll
    for (int j = 0; j < 8; j++) Fp[j] = pack16(r[j + 8], r[j]);
    #pragma unroll
    for (int k = 0; k < 16; k++) Fh[k] = r[16 + k];

    // 999 chained iterations: U = hmac(pw, U); F ^= U.
    // Absorb collapse: r[j] = c[j] + r[16+j] (9-bit OK, mix LOP3 re-masks),
    // r[16+j] = old r[j] (order-2 swap; even unroll -> pure renaming).
    #pragma unroll 4
    for (int it = 1; it < 1000; it++) {
        #pragma unroll
        for (int j = 0; j < 16; j++) {
            unsigned t = r[j];
            r[j] = c[j] + r[16 + j];
            r[16 + j] = t;
        }
        #pragma unroll
        for (int rd = 0; rd < 3; rd++) {
            #pragma unroll
            for (int i = 0; i < 32; i++)
                r[i] = (r[i] ^ (r[(i + 17) & 31] + r[(i + 11) & 31])) & 255u;
        }
        // Round 4 with F fused at operand-ready points:
        // steps 0..7 plain
        #pragma unroll
        for (int i = 0; i < 8; i++)
            r[i] = (r[i] ^ (r[(i + 17) & 31] + r[(i + 11) & 31])) & 255u;
        // steps 8..15: r[i-8] and r[i] both final -> packed pair xor
        #pragma unroll
        for (int i = 8; i < 16; i++) {
            r[i] = (r[i] ^ (r[(i + 17) & 31] + r[(i + 11) & 31])) & 255u;
            Fp[i - 8] ^= pack16(r[i], r[i - 8]);   // IMAD (fma) + LOP3 (alu)
        }
        // steps 16..31: singles
        #pragma unroll
        for (int i = 16; i < 32; i++) {
            r[i] = (r[i] ^ (r[(i + 17) & 31] + r[(i + 11) & 31])) & 255u;
            Fh[i - 16] ^= r[i];                    // LOP3 (alu)
        }
    }

    if (threadIdx.x == 0) {
        #pragma unroll
        for (int j = 0; j < 8; j++) {
            out[j]     = (float)(Fp[j] & 0xFFFFu);
            out[j + 8] = (float)(Fp[j] >> 16);
        }
        #pragma unroll
        for (int k = 0; k < 16; k++) out[16 + k] = (float)Fh[k];
    }
}

extern "C" void kernel_launch(void* const* d_in, const int* in_sizes, int n_in,
                              void* d_out, int out_size) {
    const void* password = d_in[0];
    const void* salt     = (n_in >= 2) ? d_in[1] : (const void*)((const int*)d_in[0] + 16);
    float* out           = (float*)d_out;
    Model_62955630625117_kernel<<<1, 32>>>(password, salt, out);
}